// round 1
// baseline (speedup 1.0000x reference)
#include <cuda_runtime.h>
#include <cstddef>

#define NU 100000
#define NP 50000
#define NE 2000000
#define NLAB 500000
#define HDIM 64

// ---------------- scratch (device globals; no allocation allowed) -------------
__device__ float g_xu1[NU * HDIM];    // projected user feats (layer1) / hu_proj (layer2)
__device__ float g_xp1[NP * HDIM];    // projected product feats (layer1) / hp_proj (layer2)
__device__ float g_sum_p[NP * HDIM];  // scatter accumulator (dst = product)
__device__ float g_sum_u[NU * HDIM];  // scatter accumulator (dst = user)
__device__ float g_cnt_p[NP];
__device__ float g_cnt_u[NU];
__device__ float g_hp[NP * HDIM];
__device__ float g_hu[NU * HDIM];
__device__ float g_hp2[NP * HDIM];
__device__ float g_hu2[NU * HDIM];

// ---------------- small helpers ----------------------------------------------
__device__ __forceinline__ void red4(float* p, float4 v) {
    // vectorized fp32 reduction (sm_90+): one L2 red op per 16B
    asm volatile("red.global.add.v4.f32 [%0], {%1,%2,%3,%4};"
                 :: "l"(p), "f"(v.x), "f"(v.y), "f"(v.z), "f"(v.w)
                 : "memory");
}

__global__ void zero_kernel(float* __restrict__ p, int n4) {
    int i = blockIdx.x * blockDim.x + threadIdx.x;
    if (i < n4) ((float4*)p)[i] = make_float4(0.f, 0.f, 0.f, 0.f);
}

// ---------------- generic fused GEMM: out[N,64] = X[N,K] @ W[K,64] ------------
// optional: + bias[64] + sum[N,64]/max(cnt,1), optional relu.
// Block: 256 threads -> 64 rows x 64 cols tile, 4x4 register tile per thread.
template <int K>
__global__ void gemm64(const float* __restrict__ X, const float* __restrict__ W,
                       const float* __restrict__ bias,
                       const float* __restrict__ sum, const float* __restrict__ cnt,
                       float* __restrict__ out, int N, int relu) {
    extern __shared__ float sm[];
    float* Ws = sm;            // [K][64]
    float* Xs = sm + K * 64;   // [64][K]
    int tid = threadIdx.x;
    int r0 = blockIdx.x * 64;

    // load W (K*64 floats)
    for (int f = tid; f < K * 64 / 4; f += 256)
        ((float4*)Ws)[f] = ((const float4*)W)[f];

    // load X tile (64 rows x K)
    for (int f = tid; f < 64 * K / 4; f += 256) {
        int row = f / (K / 4);
        int kq  = f % (K / 4);
        int grow = r0 + row;
        float4 v = make_float4(0.f, 0.f, 0.f, 0.f);
        if (grow < N) v = ((const float4*)(X + (size_t)grow * K))[kq];
        ((float4*)(Xs + row * K))[kq] = v;
    }
    __syncthreads();

    int tx = tid & 15;          // 16 col-groups of 4
    int ty = tid >> 4;          // 16 row-groups of 4
    int c0 = tx * 4;
    int rr = ty * 4;

    float acc[4][4];
#pragma unroll
    for (int i = 0; i < 4; i++)
#pragma unroll
        for (int j = 0; j < 4; j++) acc[i][j] = 0.f;

#pragma unroll 4
    for (int k = 0; k < K; k++) {
        float4 w = *(const float4*)&Ws[k * 64 + c0];
#pragma unroll
        for (int i = 0; i < 4; i++) {
            float x = Xs[(rr + i) * K + k];
            acc[i][0] += x * w.x;
            acc[i][1] += x * w.y;
            acc[i][2] += x * w.z;
            acc[i][3] += x * w.w;
        }
    }

#pragma unroll
    for (int i = 0; i < 4; i++) {
        int grow = r0 + rr + i;
        if (grow >= N) break;
        float4 o = make_float4(acc[i][0], acc[i][1], acc[i][2], acc[i][3]);
        if (bias) {
            o.x += bias[c0 + 0]; o.y += bias[c0 + 1];
            o.z += bias[c0 + 2]; o.w += bias[c0 + 3];
        }
        if (sum) {
            float rc = 1.f / fmaxf(cnt[grow], 1.f);
            float4 s = ((const float4*)(sum + (size_t)grow * 64))[tx];
            o.x += s.x * rc; o.y += s.y * rc; o.z += s.z * rc; o.w += s.w * rc;
        }
        if (relu) {
            o.x = fmaxf(o.x, 0.f); o.y = fmaxf(o.y, 0.f);
            o.z = fmaxf(o.z, 0.f); o.w = fmaxf(o.w, 0.f);
        }
        ((float4*)(out + (size_t)grow * 64))[tx] = o;
    }
}

// ---------------- fused bidirectional edge scatter ----------------------------
// Per edge e: SP[dst[e]] += A[src[e]]  and  SU[src[e]] += B[dst[e]]  (64 floats each).
// 16 threads per edge, edge indices staged in smem. Optionally accumulates counts.
__global__ void scatter_kernel(const int* __restrict__ src, const int* __restrict__ dst,
                               const float* __restrict__ A, const float* __restrict__ B,
                               float* __restrict__ SP, float* __restrict__ SU,
                               float* __restrict__ CP, float* __restrict__ CU,
                               int do_count) {
    __shared__ int s_src[16], s_dst[16];
    int tid = threadIdx.x;
    long e0 = (long)blockIdx.x * 16;
    if (tid < 16) {
        long e = e0 + tid;
        s_src[tid] = (e < NE) ? src[e] : -1;
    } else if (tid < 32) {
        long e = e0 + (tid - 16);
        s_dst[tid - 16] = (e < NE) ? dst[e] : -1;
    }
    __syncthreads();

    int el = tid >> 4;
    int c  = tid & 15;
    int s = s_src[el];
    if (s < 0) return;
    int d = s_dst[el];

    float4 a = __ldg(((const float4*)(A + (size_t)s * 64)) + c);
    float4 b = __ldg(((const float4*)(B + (size_t)d * 64)) + c);
    red4(SP + (size_t)d * 64 + c * 4, a);
    red4(SU + (size_t)s * 64 + c * 4, b);
    if (do_count && c == 0) {
        atomicAdd(CP + d, 1.f);
        atomicAdd(CU + s, 1.f);
    }
}

// ---------------- classifier: out[i] = dot(U[lab_u[i]], P[lab_p[i]]) ----------
__global__ void classify_kernel(const int* __restrict__ lu, const int* __restrict__ lp,
                                const float* __restrict__ U, const float* __restrict__ P,
                                float* __restrict__ out) {
    int gid = blockIdx.x * blockDim.x + threadIdx.x;
    int e = gid >> 3;   // 8 threads per label edge
    int c = gid & 7;    // each handles 8 floats (2 float4)
    if (e >= NLAB) return;
    int u = lu[e], p = lp[e];
    const float4* up = (const float4*)(U + (size_t)u * 64);
    const float4* pp = (const float4*)(P + (size_t)p * 64);
    float4 a0 = __ldg(up + c * 2), a1 = __ldg(up + c * 2 + 1);
    float4 b0 = __ldg(pp + c * 2), b1 = __ldg(pp + c * 2 + 1);
    float s = a0.x * b0.x + a0.y * b0.y + a0.z * b0.z + a0.w * b0.w
            + a1.x * b1.x + a1.y * b1.y + a1.z * b1.z + a1.w * b1.w;
    s += __shfl_down_sync(0xffffffffu, s, 4, 8);
    s += __shfl_down_sync(0xffffffffu, s, 2, 8);
    s += __shfl_down_sync(0xffffffffu, s, 1, 8);
    if (c == 0) out[e] = s;
}

// ---------------- launch ------------------------------------------------------
extern "C" void kernel_launch(void* const* d_in, const int* in_sizes, int n_in,
                              void* d_out, int out_size) {
    const float* x_user    = (const float*)d_in[0];
    const float* x_product = (const float*)d_in[1];
    const float* W1bl = (const float*)d_in[2];
    const float* b1b  = (const float*)d_in[3];
    const float* W1br = (const float*)d_in[4];
    const float* W1rl = (const float*)d_in[5];
    const float* b1r  = (const float*)d_in[6];
    const float* W1rr = (const float*)d_in[7];
    const float* W2bl = (const float*)d_in[8];
    const float* b2b  = (const float*)d_in[9];
    const float* W2br = (const float*)d_in[10];
    const float* W2rl = (const float*)d_in[11];
    const float* b2r  = (const float*)d_in[12];
    const float* W2rr = (const float*)d_in[13];
    const int* esrc = (const int*)d_in[14];
    const int* edst = (const int*)d_in[15];
    const int* lu   = (const int*)d_in[16];
    const int* lp   = (const int*)d_in[17];
    float* out = (float*)d_out;

    float *xu1, *xp1, *sp, *su, *cp, *cu, *hp, *hu, *hp2, *hu2;
    cudaGetSymbolAddress((void**)&xu1, g_xu1);
    cudaGetSymbolAddress((void**)&xp1, g_xp1);
    cudaGetSymbolAddress((void**)&sp,  g_sum_p);
    cudaGetSymbolAddress((void**)&su,  g_sum_u);
    cudaGetSymbolAddress((void**)&cp,  g_cnt_p);
    cudaGetSymbolAddress((void**)&cu,  g_cnt_u);
    cudaGetSymbolAddress((void**)&hp,  g_hp);
    cudaGetSymbolAddress((void**)&hu,  g_hu);
    cudaGetSymbolAddress((void**)&hp2, g_hp2);
    cudaGetSymbolAddress((void**)&hu2, g_hu2);

    cudaFuncSetAttribute(gemm64<128>, cudaFuncAttributeMaxDynamicSharedMemorySize,
                         2 * 128 * 64 * 4);

    const int smem64  = 2 * 64 * 64 * 4;    // 32 KB
    const int smem128 = 2 * 128 * 64 * 4;   // 64 KB
    const int gU = (NU + 63) / 64, gP = (NP + 63) / 64;
    const int gE = (NE + 15) / 16;

    // zero layer-1 accumulators + counts
    zero_kernel<<<(NP * HDIM / 4 + 255) / 256, 256>>>(sp, NP * HDIM / 4);
    zero_kernel<<<(NU * HDIM / 4 + 255) / 256, 256>>>(su, NU * HDIM / 4);
    zero_kernel<<<(NP / 4 + 255) / 256, 256>>>(cp, NP / 4);
    zero_kernel<<<(NU / 4 + 255) / 256, 256>>>(cu, NU / 4);

    // ---- layer 1 ----
    // pre-projection (mean(x)@W == mean(x@W))
    gemm64<64><<<gU, 256, smem64>>>(x_user, W1bl, nullptr, nullptr, nullptr, xu1, NU, 0);
    gemm64<128><<<gP, 256, smem128>>>(x_product, W1rl, nullptr, nullptr, nullptr, xp1, NP, 0);
    // fused bidirectional scatter + counts
    scatter_kernel<<<gE, 256>>>(esrc, edst, xu1, xp1, sp, su, cp, cu, 1);
    // combine: h = relu(sum/cnt + b + x_dst @ W_r)
    gemm64<128><<<gP, 256, smem128>>>(x_product, W1br, b1b, sp, cp, hp, NP, 1);
    gemm64<64><<<gU, 256, smem64>>>(x_user, W1rr, b1r, su, cu, hu, NU, 1);

    // ---- layer 2 ----
    zero_kernel<<<(NP * HDIM / 4 + 255) / 256, 256>>>(sp, NP * HDIM / 4);
    zero_kernel<<<(NU * HDIM / 4 + 255) / 256, 256>>>(su, NU * HDIM / 4);
    gemm64<64><<<gU, 256, smem64>>>(hu, W2bl, nullptr, nullptr, nullptr, xu1, NU, 0);
    gemm64<64><<<gP, 256, smem64>>>(hp, W2rl, nullptr, nullptr, nullptr, xp1, NP, 0);
    scatter_kernel<<<gE, 256>>>(esrc, edst, xu1, xp1, sp, su, nullptr, nullptr, 0);
    gemm64<64><<<gP, 256, smem64>>>(hp, W2br, b2b, sp, cp, hp2, NP, 0);
    gemm64<64><<<gU, 256, smem64>>>(hu, W2rr, b2r, su, cu, hu2, NU, 0);

    // ---- classifier ----
    classify_kernel<<<(NLAB * 8 + 255) / 256, 256>>>(lu, lp, hu2, hp2, out);
}

// round 2
// speedup vs baseline: 1.1459x; 1.1459x over previous
#include <cuda_runtime.h>
#include <cstddef>

#define NU 100000
#define NP 50000
#define NE 2000000
#define NLAB 500000
#define HDIM 64

// ---------------- scratch (device globals; no allocation allowed) -------------
__device__ float g_xu1[NU * HDIM];    // projected user feats
__device__ float g_xp1[NP * HDIM];    // projected product feats
__device__ float g_sum_p[NP * HDIM];  // mean-aggregated (dst = product)
__device__ float g_sum_u[NU * HDIM];  // mean-aggregated (dst = user)
__device__ float g_hp[NP * HDIM];
__device__ float g_hu[NU * HDIM];
__device__ float g_hp2[NP * HDIM];
__device__ float g_hu2[NU * HDIM];

// CSR structures (rebuilt every launch; graph-capturable, allocation-free)
__device__ int g_hist_p[NP];
__device__ int g_hist_u[NU];
__device__ int g_rowp_p[NP + 1];
__device__ int g_rowp_u[NU + 1];
__device__ int g_cur_p[NP];
__device__ int g_cur_u[NU];
__device__ int g_adj_p[NE];   // src ids grouped by dst (product)
__device__ int g_adj_u[NE];   // dst ids grouped by src (user)

// ---------------- utility ----------------------------------------------------
__global__ void zero_int_kernel(int* __restrict__ p, int n4) {
    int i = blockIdx.x * blockDim.x + threadIdx.x;
    if (i < n4) ((int4*)p)[i] = make_int4(0, 0, 0, 0);
}

// ---------------- CSR build ---------------------------------------------------
__global__ void hist_kernel(const int* __restrict__ src, const int* __restrict__ dst,
                            int* __restrict__ hp, int* __restrict__ hu) {
    int e = blockIdx.x * blockDim.x + threadIdx.x;
    if (e >= NE) return;
    atomicAdd(hp + dst[e], 1);
    atomicAdd(hu + src[e], 1);
}

// one block per array: exclusive scan (Hillis-Steele over 1024-chunks, carry in regs)
__global__ void scan2_kernel(const int* __restrict__ h0, int* __restrict__ r0, int* __restrict__ c0, int n0,
                             const int* __restrict__ h1, int* __restrict__ r1, int* __restrict__ c1, int n1) {
    const int* h = blockIdx.x ? h1 : h0;
    int* r = blockIdx.x ? r1 : r0;
    int* c = blockIdx.x ? c1 : c0;
    int n = blockIdx.x ? n1 : n0;
    __shared__ int sm[1024];
    int tid = threadIdx.x;
    int carry = 0;
    for (int base = 0; base < n; base += 1024) {
        int v = (base + tid < n) ? h[base + tid] : 0;
        sm[tid] = v;
        __syncthreads();
#pragma unroll
        for (int off = 1; off < 1024; off <<= 1) {
            int t = (tid >= off) ? sm[tid - off] : 0;
            __syncthreads();
            sm[tid] += t;
            __syncthreads();
        }
        int excl = sm[tid] - v + carry;
        if (base + tid < n) { r[base + tid] = excl; c[base + tid] = excl; }
        carry += sm[1023];
        __syncthreads();
    }
    if (tid == 0) r[n] = carry;
}

__global__ void fill_kernel(const int* __restrict__ src, const int* __restrict__ dst,
                            int* __restrict__ cur_p, int* __restrict__ cur_u,
                            int* __restrict__ adj_p, int* __restrict__ adj_u) {
    int e = blockIdx.x * blockDim.x + threadIdx.x;
    if (e >= NE) return;
    int s = src[e], d = dst[e];
    int pp = atomicAdd(cur_p + d, 1);
    adj_p[pp] = s;
    int pu = atomicAdd(cur_u + s, 1);
    adj_u[pu] = d;
}

// ---------------- gather-mean aggregation -------------------------------------
// 16 threads per node; each accumulates one float4 column across neighbors.
__global__ void gather_mean(const int* __restrict__ rowptr, const int* __restrict__ adj,
                            const float* __restrict__ A, float* __restrict__ S, int n) {
    int t = blockIdx.x * blockDim.x + threadIdx.x;
    int node = t >> 4;
    int c = t & 15;
    if (node >= n) return;
    int beg = __ldg(rowptr + node), end = __ldg(rowptr + node + 1);
    float4 acc = make_float4(0.f, 0.f, 0.f, 0.f);
    int j = beg;
    for (; j + 4 <= end; j += 4) {
        int i0 = __ldg(adj + j), i1 = __ldg(adj + j + 1);
        int i2 = __ldg(adj + j + 2), i3 = __ldg(adj + j + 3);
        float4 v0 = __ldg((const float4*)(A + (size_t)i0 * 64) + c);
        float4 v1 = __ldg((const float4*)(A + (size_t)i1 * 64) + c);
        float4 v2 = __ldg((const float4*)(A + (size_t)i2 * 64) + c);
        float4 v3 = __ldg((const float4*)(A + (size_t)i3 * 64) + c);
        acc.x += v0.x + v1.x + v2.x + v3.x;
        acc.y += v0.y + v1.y + v2.y + v3.y;
        acc.z += v0.z + v1.z + v2.z + v3.z;
        acc.w += v0.w + v1.w + v2.w + v3.w;
    }
    for (; j < end; j++) {
        int id = __ldg(adj + j);
        float4 v = __ldg((const float4*)(A + (size_t)id * 64) + c);
        acc.x += v.x; acc.y += v.y; acc.z += v.z; acc.w += v.w;
    }
    float rc = 1.f / fmaxf((float)(end - beg), 1.f);
    acc.x *= rc; acc.y *= rc; acc.z *= rc; acc.w *= rc;
    ((float4*)(S + (size_t)node * 64))[c] = acc;
}

// ---------------- generic fused GEMM: out[N,64] = X[N,K] @ W[K,64] ------------
// optional: + bias[64] + sum[N,64] (pre-averaged), optional relu.
template <int K>
__global__ void gemm64(const float* __restrict__ X, const float* __restrict__ W,
                       const float* __restrict__ bias,
                       const float* __restrict__ sum,
                       float* __restrict__ out, int N, int relu) {
    extern __shared__ float sm[];
    float* Ws = sm;            // [K][64]
    float* Xs = sm + K * 64;   // [64][K]
    int tid = threadIdx.x;
    int r0 = blockIdx.x * 64;

    for (int f = tid; f < K * 64 / 4; f += 256)
        ((float4*)Ws)[f] = ((const float4*)W)[f];

    for (int f = tid; f < 64 * K / 4; f += 256) {
        int row = f / (K / 4);
        int kq  = f % (K / 4);
        int grow = r0 + row;
        float4 v = make_float4(0.f, 0.f, 0.f, 0.f);
        if (grow < N) v = ((const float4*)(X + (size_t)grow * K))[kq];
        ((float4*)(Xs + row * K))[kq] = v;
    }
    __syncthreads();

    int tx = tid & 15;
    int ty = tid >> 4;
    int c0 = tx * 4;
    int rr = ty * 4;

    float acc[4][4];
#pragma unroll
    for (int i = 0; i < 4; i++)
#pragma unroll
        for (int j = 0; j < 4; j++) acc[i][j] = 0.f;

#pragma unroll 4
    for (int k = 0; k < K; k++) {
        float4 w = *(const float4*)&Ws[k * 64 + c0];
#pragma unroll
        for (int i = 0; i < 4; i++) {
            float x = Xs[(rr + i) * K + k];
            acc[i][0] += x * w.x;
            acc[i][1] += x * w.y;
            acc[i][2] += x * w.z;
            acc[i][3] += x * w.w;
        }
    }

#pragma unroll
    for (int i = 0; i < 4; i++) {
        int grow = r0 + rr + i;
        if (grow >= N) break;
        float4 o = make_float4(acc[i][0], acc[i][1], acc[i][2], acc[i][3]);
        if (bias) {
            o.x += bias[c0 + 0]; o.y += bias[c0 + 1];
            o.z += bias[c0 + 2]; o.w += bias[c0 + 3];
        }
        if (sum) {
            float4 s = ((const float4*)(sum + (size_t)grow * 64))[tx];
            o.x += s.x; o.y += s.y; o.z += s.z; o.w += s.w;
        }
        if (relu) {
            o.x = fmaxf(o.x, 0.f); o.y = fmaxf(o.y, 0.f);
            o.z = fmaxf(o.z, 0.f); o.w = fmaxf(o.w, 0.f);
        }
        ((float4*)(out + (size_t)grow * 64))[tx] = o;
    }
}

// ---------------- classifier: out[i] = dot(U[lab_u[i]], P[lab_p[i]]) ----------
__global__ void classify_kernel(const int* __restrict__ lu, const int* __restrict__ lp,
                                const float* __restrict__ U, const float* __restrict__ P,
                                float* __restrict__ out) {
    int gid = blockIdx.x * blockDim.x + threadIdx.x;
    int e = gid >> 3;
    int c = gid & 7;
    if (e >= NLAB) return;
    int u = lu[e], p = lp[e];
    const float4* up = (const float4*)(U + (size_t)u * 64);
    const float4* pp = (const float4*)(P + (size_t)p * 64);
    float4 a0 = __ldg(up + c * 2), a1 = __ldg(up + c * 2 + 1);
    float4 b0 = __ldg(pp + c * 2), b1 = __ldg(pp + c * 2 + 1);
    float s = a0.x * b0.x + a0.y * b0.y + a0.z * b0.z + a0.w * b0.w
            + a1.x * b1.x + a1.y * b1.y + a1.z * b1.z + a1.w * b1.w;
    s += __shfl_down_sync(0xffffffffu, s, 4, 8);
    s += __shfl_down_sync(0xffffffffu, s, 2, 8);
    s += __shfl_down_sync(0xffffffffu, s, 1, 8);
    if (c == 0) out[e] = s;
}

// ---------------- launch ------------------------------------------------------
extern "C" void kernel_launch(void* const* d_in, const int* in_sizes, int n_in,
                              void* d_out, int out_size) {
    const float* x_user    = (const float*)d_in[0];
    const float* x_product = (const float*)d_in[1];
    const float* W1bl = (const float*)d_in[2];
    const float* b1b  = (const float*)d_in[3];
    const float* W1br = (const float*)d_in[4];
    const float* W1rl = (const float*)d_in[5];
    const float* b1r  = (const float*)d_in[6];
    const float* W1rr = (const float*)d_in[7];
    const float* W2bl = (const float*)d_in[8];
    const float* b2b  = (const float*)d_in[9];
    const float* W2br = (const float*)d_in[10];
    const float* W2rl = (const float*)d_in[11];
    const float* b2r  = (const float*)d_in[12];
    const float* W2rr = (const float*)d_in[13];
    const int* esrc = (const int*)d_in[14];
    const int* edst = (const int*)d_in[15];
    const int* lu   = (const int*)d_in[16];
    const int* lp   = (const int*)d_in[17];
    float* out = (float*)d_out;

    float *xu1, *xp1, *sp, *su, *hp, *hu, *hp2, *hu2;
    int *histp, *histu, *rowp, *rowu, *curp, *curu, *adjp, *adju;
    cudaGetSymbolAddress((void**)&xu1, g_xu1);
    cudaGetSymbolAddress((void**)&xp1, g_xp1);
    cudaGetSymbolAddress((void**)&sp,  g_sum_p);
    cudaGetSymbolAddress((void**)&su,  g_sum_u);
    cudaGetSymbolAddress((void**)&hp,  g_hp);
    cudaGetSymbolAddress((void**)&hu,  g_hu);
    cudaGetSymbolAddress((void**)&hp2, g_hp2);
    cudaGetSymbolAddress((void**)&hu2, g_hu2);
    cudaGetSymbolAddress((void**)&histp, g_hist_p);
    cudaGetSymbolAddress((void**)&histu, g_hist_u);
    cudaGetSymbolAddress((void**)&rowp, g_rowp_p);
    cudaGetSymbolAddress((void**)&rowu, g_rowp_u);
    cudaGetSymbolAddress((void**)&curp, g_cur_p);
    cudaGetSymbolAddress((void**)&curu, g_cur_u);
    cudaGetSymbolAddress((void**)&adjp, g_adj_p);
    cudaGetSymbolAddress((void**)&adju, g_adj_u);

    cudaFuncSetAttribute(gemm64<128>, cudaFuncAttributeMaxDynamicSharedMemorySize,
                         2 * 128 * 64 * 4);

    const int smem64  = 2 * 64 * 64 * 4;    // 32 KB
    const int smem128 = 2 * 128 * 64 * 4;   // 64 KB
    const int gU = (NU + 63) / 64, gP = (NP + 63) / 64;
    const int gE = (NE + 255) / 256;
    const int gAggP = (NP * 16 + 255) / 256;
    const int gAggU = (NU * 16 + 255) / 256;

    // ---- CSR build (both directions) ----
    zero_int_kernel<<<(NP / 4 + 255) / 256, 256>>>(histp, NP / 4);
    zero_int_kernel<<<(NU / 4 + 255) / 256, 256>>>(histu, NU / 4);
    hist_kernel<<<gE, 256>>>(esrc, edst, histp, histu);
    scan2_kernel<<<2, 1024>>>(histp, rowp, curp, NP, histu, rowu, curu, NU);
    fill_kernel<<<gE, 256>>>(esrc, edst, curp, curu, adjp, adju);

    // ---- layer 1 ----
    gemm64<64><<<gU, 256, smem64>>>(x_user, W1bl, nullptr, nullptr, xu1, NU, 0);
    gemm64<128><<<gP, 256, smem128>>>(x_product, W1rl, nullptr, nullptr, xp1, NP, 0);
    gather_mean<<<gAggP, 256>>>(rowp, adjp, xu1, sp, NP);
    gather_mean<<<gAggU, 256>>>(rowu, adju, xp1, su, NU);
    gemm64<128><<<gP, 256, smem128>>>(x_product, W1br, b1b, sp, hp, NP, 1);
    gemm64<64><<<gU, 256, smem64>>>(x_user, W1rr, b1r, su, hu, NU, 1);

    // ---- layer 2 ----
    gemm64<64><<<gU, 256, smem64>>>(hu, W2bl, nullptr, nullptr, xu1, NU, 0);
    gemm64<64><<<gP, 256, smem64>>>(hp, W2rl, nullptr, nullptr, xp1, NP, 0);
    gather_mean<<<gAggP, 256>>>(rowp, adjp, xu1, sp, NP);
    gather_mean<<<gAggU, 256>>>(rowu, adju, xp1, su, NU);
    gemm64<64><<<gP, 256, smem64>>>(hp, W2br, b2b, sp, hp2, NP, 0);
    gemm64<64><<<gU, 256, smem64>>>(hu, W2rr, b2r, su, hu2, NU, 0);

    // ---- classifier ----
    classify_kernel<<<(NLAB * 8 + 255) / 256, 256>>>(lu, lp, hu2, hp2, out);
}

// round 5
// speedup vs baseline: 1.5826x; 1.3811x over previous
#include <cuda_runtime.h>
#include <cuda_fp16.h>
#include <cstddef>

#define NU 100000
#define NP 50000
#define NE 2000000
#define NLAB 500000
#define HDIM 64

#define CHUNK 4096
#define CP_CHUNKS ((NP + CHUNK - 1) / CHUNK)   // 13
#define CU_CHUNKS ((NU + CHUNK - 1) / CHUNK)   // 25

// ---------------- scratch (device globals; no allocation allowed) -------------
__device__ __half g_xu1[NU * HDIM];   // projected user feats (fp16)
__device__ __half g_xp1[NP * HDIM];   // projected product feats (fp16)
__device__ float g_sum_p[NP * HDIM];  // mean-aggregated (dst = product)
__device__ float g_sum_u[NU * HDIM];  // mean-aggregated (dst = user)
__device__ float g_hp[NP * HDIM];
__device__ float g_hu[NU * HDIM];
__device__ float g_hp2[NP * HDIM];
__device__ float g_hu2[NU * HDIM];

__device__ int g_hist_p[NP];
__device__ int g_hist_u[NU];
__device__ int g_rowp_p[NP + 1];
__device__ int g_rowp_u[NU + 1];
__device__ int g_cur_p[NP];
__device__ int g_cur_u[NU];
__device__ int g_adj_p[NE];
__device__ int g_adj_u[NE];
__device__ int g_aux_p[32];
__device__ int g_aux_u[32];

// ---------------- utility ----------------------------------------------------
__global__ void zero_int_kernel(int* __restrict__ p, int n4) {
    int i = blockIdx.x * blockDim.x + threadIdx.x;
    if (i < n4) ((int4*)p)[i] = make_int4(0, 0, 0, 0);
}

// ---------------- CSR build ---------------------------------------------------
__global__ void hist_kernel(const int* __restrict__ src, const int* __restrict__ dst,
                            int* __restrict__ hp, int* __restrict__ hu) {
    int e = blockIdx.x * blockDim.x + threadIdx.x;
    if (e >= NE) return;
    atomicAdd(hp + dst[e], 1);
    atomicAdd(hu + src[e], 1);
}

// pass1: per-chunk exclusive scan (1024 thr x 4 elems), chunk total -> aux
__global__ void scan_pass1(const int* __restrict__ hP, int* __restrict__ rP, int* __restrict__ auxP,
                           const int* __restrict__ hU, int* __restrict__ rU, int* __restrict__ auxU) {
    int b = blockIdx.x;
    const int* h; int* r; int* aux; int n; int cid;
    if (b < CP_CHUNKS) { h = hP; r = rP; aux = auxP; n = NP; cid = b; }
    else               { h = hU; r = rU; aux = auxU; n = NU; cid = b - CP_CHUNKS; }

    int tid = threadIdx.x;
    int base = cid * CHUNK + tid * 4;
    int4 v = make_int4(0, 0, 0, 0);
    if (base < n) v = *(const int4*)(h + base);   // n % 4 == 0 for both arrays
    int tsum = v.x + v.y + v.z + v.w;

    unsigned lane = tid & 31, wid = tid >> 5;
    int inc = tsum;
#pragma unroll
    for (int off = 1; off < 32; off <<= 1) {
        int t = __shfl_up_sync(0xffffffffu, inc, off);
        if (lane >= off) inc += t;
    }
    __shared__ int s_w[32];
    if (lane == 31) s_w[wid] = inc;
    __syncthreads();
    if (tid < 32) {
        int w = s_w[tid];
        int winc = w;
#pragma unroll
        for (int off = 1; off < 32; off <<= 1) {
            int t = __shfl_up_sync(0xffffffffu, winc, off);
            if (tid >= off) winc += t;
        }
        s_w[tid] = winc - w;          // exclusive warp base
        if (tid == 31) aux[cid] = winc; // chunk total
    }
    __syncthreads();
    int tbase = s_w[wid] + inc - tsum;
    if (base < n) {
        int4 o;
        o.x = tbase;
        o.y = tbase + v.x;
        o.z = o.y + v.y;
        o.w = o.z + v.z;
        *(int4*)(r + base) = o;
    }
}

// pass2: scan the (<=32) chunk totals, write grand total to rowptr[n]
__global__ void scan_pass2(int* __restrict__ auxP, int* __restrict__ rP,
                           int* __restrict__ auxU, int* __restrict__ rU) {
    int* aux; int* r; int cnt; int n;
    if (blockIdx.x == 0) { aux = auxP; r = rP; cnt = CP_CHUNKS; n = NP; }
    else                 { aux = auxU; r = rU; cnt = CU_CHUNKS; n = NU; }
    int tid = threadIdx.x;
    int a = (tid < cnt) ? aux[tid] : 0;
    int inc = a;
#pragma unroll
    for (int off = 1; off < 32; off <<= 1) {
        int t = __shfl_up_sync(0xffffffffu, inc, off);
        if (tid >= off) inc += t;
    }
    if (tid < cnt) aux[tid] = inc - a;
    if (tid == 31) r[n] = inc;
}

// pass3: add chunk offsets, duplicate into cursor array
__global__ void scan_pass3(int* __restrict__ rP, const int* __restrict__ auxP, int* __restrict__ cP,
                           int* __restrict__ rU, const int* __restrict__ auxU, int* __restrict__ cU) {
    int b = blockIdx.x;
    int* r; const int* aux; int* c; int n; int cid;
    if (b < CP_CHUNKS) { r = rP; aux = auxP; c = cP; n = NP; cid = b; }
    else               { r = rU; aux = auxU; c = cU; n = NU; cid = b - CP_CHUNKS; }
    int tid = threadIdx.x;
    int base = cid * CHUNK + tid * 4;
    if (base >= n) return;
    int off = aux[cid];
    int4 v = *(const int4*)(r + base);
    v.x += off; v.y += off; v.z += off; v.w += off;
    *(int4*)(r + base) = v;
    *(int4*)(c + base) = v;
}

__global__ void fill_kernel(const int* __restrict__ src, const int* __restrict__ dst,
                            int* __restrict__ cur_p, int* __restrict__ cur_u,
                            int* __restrict__ adj_p, int* __restrict__ adj_u) {
    int e = blockIdx.x * blockDim.x + threadIdx.x;
    if (e >= NE) return;
    int s = src[e], d = dst[e];
    int pp = atomicAdd(cur_p + d, 1);
    adj_p[pp] = s;
    int pu = atomicAdd(cur_u + s, 1);
    adj_u[pu] = d;
}

// ---------------- gather-mean aggregation (fp16 source rows) -------------------
// 8 threads per node; each handles 8 halves (16B). Accumulate fp32, write fp32 mean.
__global__ void gather_mean_half(const int* __restrict__ rowptr, const int* __restrict__ adj,
                                 const __half* __restrict__ A, float* __restrict__ S, int n) {
    int t = blockIdx.x * blockDim.x + threadIdx.x;
    int node = t >> 3;
    int c = t & 7;
    if (node >= n) return;
    int beg = __ldg(rowptr + node), end = __ldg(rowptr + node + 1);
    float acc[8];
#pragma unroll
    for (int i = 0; i < 8; i++) acc[i] = 0.f;

    int j = beg;
    for (; j + 4 <= end; j += 4) {
        int i0 = __ldg(adj + j), i1 = __ldg(adj + j + 1);
        int i2 = __ldg(adj + j + 2), i3 = __ldg(adj + j + 3);
        uint4 r0 = __ldg((const uint4*)(A + (size_t)i0 * 64) + c);
        uint4 r1 = __ldg((const uint4*)(A + (size_t)i1 * 64) + c);
        uint4 r2 = __ldg((const uint4*)(A + (size_t)i2 * 64) + c);
        uint4 r3 = __ldg((const uint4*)(A + (size_t)i3 * 64) + c);
        const uint4* rs[4] = {&r0, &r1, &r2, &r3};
#pragma unroll
        for (int q = 0; q < 4; q++) {
            const unsigned* u = (const unsigned*)rs[q];
#pragma unroll
            for (int k = 0; k < 4; k++) {
                float2 f = __half22float2(*(const __half2*)&u[k]);
                acc[k * 2] += f.x;
                acc[k * 2 + 1] += f.y;
            }
        }
    }
    for (; j < end; j++) {
        int id = __ldg(adj + j);
        uint4 r = __ldg((const uint4*)(A + (size_t)id * 64) + c);
        const unsigned* u = (const unsigned*)&r;
#pragma unroll
        for (int k = 0; k < 4; k++) {
            float2 f = __half22float2(*(const __half2*)&u[k]);
            acc[k * 2] += f.x;
            acc[k * 2 + 1] += f.y;
        }
    }
    float rc = 1.f / fmaxf((float)(end - beg), 1.f);
    float4 o0 = make_float4(acc[0] * rc, acc[1] * rc, acc[2] * rc, acc[3] * rc);
    float4 o1 = make_float4(acc[4] * rc, acc[5] * rc, acc[6] * rc, acc[7] * rc);
    float4* dst = (float4*)(S + (size_t)node * 64) + c * 2;
    dst[0] = o0;
    dst[1] = o1;
}

// ---------------- generic fused GEMM: out[N,64] = X[N,K] @ W[K,64] ------------
// HALF_OUT: write __half rows (projection path). Else fp32 (+bias+sum+relu).
template <int K, bool HALF_OUT>
__global__ void gemm64(const float* __restrict__ X, const float* __restrict__ W,
                       const float* __restrict__ bias,
                       const float* __restrict__ sum,
                       void* __restrict__ out, int N, int relu) {
    extern __shared__ float sm[];
    float* Ws = sm;            // [K][64]
    float* Xs = sm + K * 64;   // [64][K]
    int tid = threadIdx.x;
    int r0 = blockIdx.x * 64;

    for (int f = tid; f < K * 64 / 4; f += 256)
        ((float4*)Ws)[f] = ((const float4*)W)[f];

    for (int f = tid; f < 64 * K / 4; f += 256) {
        int row = f / (K / 4);
        int kq  = f % (K / 4);
        int grow = r0 + row;
        float4 v = make_float4(0.f, 0.f, 0.f, 0.f);
        if (grow < N) v = ((const float4*)(X + (size_t)grow * K))[kq];
        ((float4*)(Xs + row * K))[kq] = v;
    }
    __syncthreads();

    int tx = tid & 15;
    int ty = tid >> 4;
    int c0 = tx * 4;
    int rr = ty * 4;

    float acc[4][4];
#pragma unroll
    for (int i = 0; i < 4; i++)
#pragma unroll
        for (int j = 0; j < 4; j++) acc[i][j] = 0.f;

#pragma unroll 4
    for (int k = 0; k < K; k++) {
        float4 w = *(const float4*)&Ws[k * 64 + c0];
#pragma unroll
        for (int i = 0; i < 4; i++) {
            float x = Xs[(rr + i) * K + k];
            acc[i][0] += x * w.x;
            acc[i][1] += x * w.y;
            acc[i][2] += x * w.z;
            acc[i][3] += x * w.w;
        }
    }

#pragma unroll
    for (int i = 0; i < 4; i++) {
        int grow = r0 + rr + i;
        if (grow >= N) break;
        float4 o = make_float4(acc[i][0], acc[i][1], acc[i][2], acc[i][3]);
        if (!HALF_OUT) {
            if (bias) {
                o.x += bias[c0 + 0]; o.y += bias[c0 + 1];
                o.z += bias[c0 + 2]; o.w += bias[c0 + 3];
            }
            if (sum) {
                float4 s = ((const float4*)(sum + (size_t)grow * 64))[tx];
                o.x += s.x; o.y += s.y; o.z += s.z; o.w += s.w;
            }
            if (relu) {
                o.x = fmaxf(o.x, 0.f); o.y = fmaxf(o.y, 0.f);
                o.z = fmaxf(o.z, 0.f); o.w = fmaxf(o.w, 0.f);
            }
            ((float4*)((float*)out + (size_t)grow * 64))[tx] = o;
        } else {
            __half2 h0 = __floats2half2_rn(o.x, o.y);
            __half2 h1 = __floats2half2_rn(o.z, o.w);
            uint2 pk;
            pk.x = *(unsigned*)&h0;
            pk.y = *(unsigned*)&h1;
            ((uint2*)((__half*)out + (size_t)grow * 64))[tx] = pk;
        }
    }
}

// ---------------- classifier: out[i] = dot(U[lab_u[i]], P[lab_p[i]]) ----------
__global__ void classify_kernel(const int* __restrict__ lu, const int* __restrict__ lp,
                                const float* __restrict__ U, const float* __restrict__ P,
                                float* __restrict__ out) {
    int gid = blockIdx.x * blockDim.x + threadIdx.x;
    int e = gid >> 3;
    int c = gid & 7;
    if (e >= NLAB) return;
    int u = lu[e], p = lp[e];
    const float4* up = (const float4*)(U + (size_t)u * 64);
    const float4* pp = (const float4*)(P + (size_t)p * 64);
    float4 a0 = __ldg(up + c * 2), a1 = __ldg(up + c * 2 + 1);
    float4 b0 = __ldg(pp + c * 2), b1 = __ldg(pp + c * 2 + 1);
    float s = a0.x * b0.x + a0.y * b0.y + a0.z * b0.z + a0.w * b0.w
            + a1.x * b1.x + a1.y * b1.y + a1.z * b1.z + a1.w * b1.w;
    s += __shfl_down_sync(0xffffffffu, s, 4, 8);
    s += __shfl_down_sync(0xffffffffu, s, 2, 8);
    s += __shfl_down_sync(0xffffffffu, s, 1, 8);
    if (c == 0) out[e] = s;
}

// ---------------- launch ------------------------------------------------------
extern "C" void kernel_launch(void* const* d_in, const int* in_sizes, int n_in,
                              void* d_out, int out_size) {
    const float* x_user    = (const float*)d_in[0];
    const float* x_product = (const float*)d_in[1];
    const float* W1bl = (const float*)d_in[2];
    const float* b1b  = (const float*)d_in[3];
    const float* W1br = (const float*)d_in[4];
    const float* W1rl = (const float*)d_in[5];
    const float* b1r  = (const float*)d_in[6];
    const float* W1rr = (const float*)d_in[7];
    const float* W2bl = (const float*)d_in[8];
    const float* b2b  = (const float*)d_in[9];
    const float* W2br = (const float*)d_in[10];
    const float* W2rl = (const float*)d_in[11];
    const float* b2r  = (const float*)d_in[12];
    const float* W2rr = (const float*)d_in[13];
    const int* esrc = (const int*)d_in[14];
    const int* edst = (const int*)d_in[15];
    const int* lu   = (const int*)d_in[16];
    const int* lp   = (const int*)d_in[17];
    float* out = (float*)d_out;

    __half *xu1, *xp1;
    float *sp, *su, *hp, *hu, *hp2, *hu2;
    int *histp, *histu, *rowp, *rowu, *curp, *curu, *adjp, *adju, *auxp, *auxu;
    cudaGetSymbolAddress((void**)&xu1, g_xu1);
    cudaGetSymbolAddress((void**)&xp1, g_xp1);
    cudaGetSymbolAddress((void**)&sp,  g_sum_p);
    cudaGetSymbolAddress((void**)&su,  g_sum_u);
    cudaGetSymbolAddress((void**)&hp,  g_hp);
    cudaGetSymbolAddress((void**)&hu,  g_hu);
    cudaGetSymbolAddress((void**)&hp2, g_hp2);
    cudaGetSymbolAddress((void**)&hu2, g_hu2);
    cudaGetSymbolAddress((void**)&histp, g_hist_p);
    cudaGetSymbolAddress((void**)&histu, g_hist_u);
    cudaGetSymbolAddress((void**)&rowp, g_rowp_p);
    cudaGetSymbolAddress((void**)&rowu, g_rowp_u);
    cudaGetSymbolAddress((void**)&curp, g_cur_p);
    cudaGetSymbolAddress((void**)&curu, g_cur_u);
    cudaGetSymbolAddress((void**)&adjp, g_adj_p);
    cudaGetSymbolAddress((void**)&adju, g_adj_u);
    cudaGetSymbolAddress((void**)&auxp, g_aux_p);
    cudaGetSymbolAddress((void**)&auxu, g_aux_u);

    cudaFuncSetAttribute((const void*)gemm64<128, true>,
                         cudaFuncAttributeMaxDynamicSharedMemorySize, 2 * 128 * 64 * 4);
    cudaFuncSetAttribute((const void*)gemm64<128, false>,
                         cudaFuncAttributeMaxDynamicSharedMemorySize, 2 * 128 * 64 * 4);

    const int smem64  = 2 * 64 * 64 * 4;    // 32 KB
    const int smem128 = 2 * 128 * 64 * 4;   // 64 KB
    const int gU = (NU + 63) / 64, gP = (NP + 63) / 64;
    const int gE = (NE + 255) / 256;
    const int gAggP = (NP * 8 + 255) / 256;
    const int gAggU = (NU * 8 + 255) / 256;
    const int gScan = CP_CHUNKS + CU_CHUNKS;

    // ---- CSR build (both directions) ----
    zero_int_kernel<<<(NP / 4 + 255) / 256, 256>>>(histp, NP / 4);
    zero_int_kernel<<<(NU / 4 + 255) / 256, 256>>>(histu, NU / 4);
    hist_kernel<<<gE, 256>>>(esrc, edst, histp, histu);
    scan_pass1<<<gScan, 1024>>>(histp, rowp, auxp, histu, rowu, auxu);
    scan_pass2<<<2, 32>>>(auxp, rowp, auxu, rowu);
    scan_pass3<<<gScan, 1024>>>(rowp, auxp, curp, rowu, auxu, curu);
    fill_kernel<<<gE, 256>>>(esrc, edst, curp, curu, adjp, adju);

    // ---- layer 1 ----
    gemm64<64, true><<<gU, 256, smem64>>>(x_user, W1bl, nullptr, nullptr, xu1, NU, 0);
    gemm64<128, true><<<gP, 256, smem128>>>(x_product, W1rl, nullptr, nullptr, xp1, NP, 0);
    gather_mean_half<<<gAggP, 256>>>(rowp, adjp, xu1, sp, NP);
    gather_mean_half<<<gAggU, 256>>>(rowu, adju, xp1, su, NU);
    gemm64<128, false><<<gP, 256, smem128>>>(x_product, W1br, b1b, sp, hp, NP, 1);
    gemm64<64, false><<<gU, 256, smem64>>>(x_user, W1rr, b1r, su, hu, NU, 1);

    // ---- layer 2 ----
    gemm64<64, true><<<gU, 256, smem64>>>(hu, W2bl, nullptr, nullptr, xu1, NU, 0);
    gemm64<64, true><<<gP, 256, smem64>>>(hp, W2rl, nullptr, nullptr, xp1, NP, 0);
    gather_mean_half<<<gAggP, 256>>>(rowp, adjp, xu1, sp, NP);
    gather_mean_half<<<gAggU, 256>>>(rowu, adju, xp1, su, NU);
    gemm64<64, false><<<gP, 256, smem64>>>(hp, W2br, b2b, sp, hp2, NP, 0);
    gemm64<64, false><<<gU, 256, smem64>>>(hu, W2rr, b2r, su, hu2, NU, 0);

    // ---- classifier ----
    classify_kernel<<<(NLAB * 8 + 255) / 256, 256>>>(lu, lp, hu2, hp2, out);
}

// round 6
// speedup vs baseline: 2.0550x; 1.2985x over previous
#include <cuda_runtime.h>
#include <cuda_fp16.h>
#include <mma.h>
#include <cstddef>

using namespace nvcuda;

#define NU 100000
#define NP 50000
#define NE 2000000
#define NLAB 500000
#define HDIM 64

#define CHUNK 4096
#define CP_CHUNKS ((NP + CHUNK - 1) / CHUNK)   // 13
#define CU_CHUNKS ((NU + CHUNK - 1) / CHUNK)   // 25

// ---------------- scratch (device globals; no allocation allowed) -------------
__device__ __half g_xu_h[NU * 64];     // fp16 copy of x_user
__device__ __half g_xp_h[NP * 128];    // fp16 copy of x_product
__device__ __half g_xu1[NU * HDIM];    // projected user feats (fp16)
__device__ __half g_xp1[NP * HDIM];    // projected product feats (fp16)
__device__ float g_sum_p[NP * HDIM];   // mean-aggregated (fp32)
__device__ float g_sum_u[NU * HDIM];
__device__ __half g_hp[NP * HDIM];
__device__ __half g_hu[NU * HDIM];
__device__ __half g_hp2[NP * HDIM];
__device__ __half g_hu2[NU * HDIM];

__device__ int g_hist_p[NP];
__device__ int g_hist_u[NU];
__device__ int g_rowp_p[NP + 1];
__device__ int g_rowp_u[NU + 1];
__device__ int g_cur_p[NP];
__device__ int g_cur_u[NU];
__device__ int g_adj_p[NE];
__device__ int g_adj_u[NE];
__device__ int g_aux_p[32];
__device__ int g_aux_u[32];

// ---------------- utility ----------------------------------------------------
__global__ void zero_int_kernel(int* __restrict__ p, int n4) {
    int i = blockIdx.x * blockDim.x + threadIdx.x;
    if (i < n4) ((int4*)p)[i] = make_int4(0, 0, 0, 0);
}

__global__ void conv_half_kernel(const float* __restrict__ in, __half* __restrict__ out, int n4) {
    int i = blockIdx.x * blockDim.x + threadIdx.x;
    if (i >= n4) return;
    float4 v = ((const float4*)in)[i];
    __half2 h0 = __floats2half2_rn(v.x, v.y);
    __half2 h1 = __floats2half2_rn(v.z, v.w);
    uint2 pk;
    pk.x = *(unsigned*)&h0;
    pk.y = *(unsigned*)&h1;
    ((uint2*)out)[i] = pk;
}

// ---------------- CSR build ---------------------------------------------------
__global__ void hist_kernel(const int* __restrict__ src, const int* __restrict__ dst,
                            int* __restrict__ hp, int* __restrict__ hu) {
    int e = blockIdx.x * blockDim.x + threadIdx.x;
    if (e >= NE) return;
    atomicAdd(hp + dst[e], 1);
    atomicAdd(hu + src[e], 1);
}

__global__ void scan_pass1(const int* __restrict__ hP, int* __restrict__ rP, int* __restrict__ auxP,
                           const int* __restrict__ hU, int* __restrict__ rU, int* __restrict__ auxU) {
    int b = blockIdx.x;
    const int* h; int* r; int* aux; int n; int cid;
    if (b < CP_CHUNKS) { h = hP; r = rP; aux = auxP; n = NP; cid = b; }
    else               { h = hU; r = rU; aux = auxU; n = NU; cid = b - CP_CHUNKS; }

    int tid = threadIdx.x;
    int base = cid * CHUNK + tid * 4;
    int4 v = make_int4(0, 0, 0, 0);
    if (base < n) v = *(const int4*)(h + base);
    int tsum = v.x + v.y + v.z + v.w;

    unsigned lane = tid & 31, wid = tid >> 5;
    int inc = tsum;
#pragma unroll
    for (int off = 1; off < 32; off <<= 1) {
        int t = __shfl_up_sync(0xffffffffu, inc, off);
        if (lane >= off) inc += t;
    }
    __shared__ int s_w[32];
    if (lane == 31) s_w[wid] = inc;
    __syncthreads();
    if (tid < 32) {
        int w = s_w[tid];
        int winc = w;
#pragma unroll
        for (int off = 1; off < 32; off <<= 1) {
            int t = __shfl_up_sync(0xffffffffu, winc, off);
            if (tid >= off) winc += t;
        }
        s_w[tid] = winc - w;
        if (tid == 31) aux[cid] = winc;
    }
    __syncthreads();
    int tbase = s_w[wid] + inc - tsum;
    if (base < n) {
        int4 o;
        o.x = tbase;
        o.y = tbase + v.x;
        o.z = o.y + v.y;
        o.w = o.z + v.z;
        *(int4*)(r + base) = o;
    }
}

__global__ void scan_pass2(int* __restrict__ auxP, int* __restrict__ rP,
                           int* __restrict__ auxU, int* __restrict__ rU) {
    int* aux; int* r; int cnt; int n;
    if (blockIdx.x == 0) { aux = auxP; r = rP; cnt = CP_CHUNKS; n = NP; }
    else                 { aux = auxU; r = rU; cnt = CU_CHUNKS; n = NU; }
    int tid = threadIdx.x;
    int a = (tid < cnt) ? aux[tid] : 0;
    int inc = a;
#pragma unroll
    for (int off = 1; off < 32; off <<= 1) {
        int t = __shfl_up_sync(0xffffffffu, inc, off);
        if (tid >= off) inc += t;
    }
    if (tid < cnt) aux[tid] = inc - a;
    if (tid == 31) r[n] = inc;
}

__global__ void scan_pass3(int* __restrict__ rP, const int* __restrict__ auxP, int* __restrict__ cP,
                           int* __restrict__ rU, const int* __restrict__ auxU, int* __restrict__ cU) {
    int b = blockIdx.x;
    int* r; const int* aux; int* c; int n; int cid;
    if (b < CP_CHUNKS) { r = rP; aux = auxP; c = cP; n = NP; cid = b; }
    else               { r = rU; aux = auxU; c = cU; n = NU; cid = b - CP_CHUNKS; }
    int tid = threadIdx.x;
    int base = cid * CHUNK + tid * 4;
    if (base >= n) return;
    int off = aux[cid];
    int4 v = *(const int4*)(r + base);
    v.x += off; v.y += off; v.z += off; v.w += off;
    *(int4*)(r + base) = v;
    *(int4*)(c + base) = v;
}

__global__ void fill_kernel(const int* __restrict__ src, const int* __restrict__ dst,
                            int* __restrict__ cur_p, int* __restrict__ cur_u,
                            int* __restrict__ adj_p, int* __restrict__ adj_u) {
    int e = blockIdx.x * blockDim.x + threadIdx.x;
    if (e >= NE) return;
    int s = src[e], d = dst[e];
    int pp = atomicAdd(cur_p + d, 1);
    adj_p[pp] = s;
    int pu = atomicAdd(cur_u + s, 1);
    adj_u[pu] = d;
}

// ---------------- gather-mean aggregation (fp16 source rows) -------------------
__global__ void gather_mean_half(const int* __restrict__ rowptr, const int* __restrict__ adj,
                                 const __half* __restrict__ A, float* __restrict__ S, int n) {
    int t = blockIdx.x * blockDim.x + threadIdx.x;
    int node = t >> 3;
    int c = t & 7;
    if (node >= n) return;
    int beg = __ldg(rowptr + node), end = __ldg(rowptr + node + 1);
    float acc[8];
#pragma unroll
    for (int i = 0; i < 8; i++) acc[i] = 0.f;

    int j = beg;
    for (; j + 4 <= end; j += 4) {
        int i0 = __ldg(adj + j), i1 = __ldg(adj + j + 1);
        int i2 = __ldg(adj + j + 2), i3 = __ldg(adj + j + 3);
        uint4 r0 = __ldg((const uint4*)(A + (size_t)i0 * 64) + c);
        uint4 r1 = __ldg((const uint4*)(A + (size_t)i1 * 64) + c);
        uint4 r2 = __ldg((const uint4*)(A + (size_t)i2 * 64) + c);
        uint4 r3 = __ldg((const uint4*)(A + (size_t)i3 * 64) + c);
        const uint4* rs[4] = {&r0, &r1, &r2, &r3};
#pragma unroll
        for (int q = 0; q < 4; q++) {
            const unsigned* u = (const unsigned*)rs[q];
#pragma unroll
            for (int k = 0; k < 4; k++) {
                float2 f = __half22float2(*(const __half2*)&u[k]);
                acc[k * 2] += f.x;
                acc[k * 2 + 1] += f.y;
            }
        }
    }
    for (; j < end; j++) {
        int id = __ldg(adj + j);
        uint4 r = __ldg((const uint4*)(A + (size_t)id * 64) + c);
        const unsigned* u = (const unsigned*)&r;
#pragma unroll
        for (int k = 0; k < 4; k++) {
            float2 f = __half22float2(*(const __half2*)&u[k]);
            acc[k * 2] += f.x;
            acc[k * 2 + 1] += f.y;
        }
    }
    float rc = 1.f / fmaxf((float)(end - beg), 1.f);
    float4 o0 = make_float4(acc[0] * rc, acc[1] * rc, acc[2] * rc, acc[3] * rc);
    float4 o1 = make_float4(acc[4] * rc, acc[5] * rc, acc[6] * rc, acc[7] * rc);
    float4* dst = (float4*)(S + (size_t)node * 64) + c * 2;
    dst[0] = o0;
    dst[1] = o1;
}

// ---------------- tensor-core GEMM: out[N,64](fp16) = X[N,K](fp16) @ W[K,64](fp32->fp16)
// 64x64 tile/block, 8 warps (4x2), wmma 16x16x16 fp16->fp32.
// Optional fp32 epilogue: + bias + sum (pre-averaged), optional relu.
template <int K, bool HAS_SUM, bool RELU>
__global__ void gemm_wmma(const __half* __restrict__ X, const float* __restrict__ W,
                          const float* __restrict__ bias, const float* __restrict__ sum,
                          __half* __restrict__ out, int N) {
    constexpr int LDX = K + 16;   // halves; multiple of 16
    constexpr int LDW = 80;       // halves
    constexpr int LDC = 80;       // floats
    extern __shared__ char smem_raw[];
    __half* Xs = (__half*)smem_raw;                          // 64 x LDX
    __half* Ws = (__half*)(smem_raw + 64 * LDX * 2);         // K x LDW
    float*  Cs = (float*)smem_raw;                           // 64 x LDC (overlaps; used after sync)

    int tid = threadIdx.x;
    int wid = tid >> 5;
    int r0 = blockIdx.x * 64;

    // load + convert W (K x 64 fp32 -> fp16 smem)
    for (int f = tid; f < K * 16; f += 256) {
        int row = f >> 4, c4 = f & 15;
        float4 w = ((const float4*)(W + row * 64))[c4];
        __half2 h0 = __floats2half2_rn(w.x, w.y);
        __half2 h1 = __floats2half2_rn(w.z, w.w);
        *(__half2*)&Ws[row * LDW + c4 * 4] = h0;
        *(__half2*)&Ws[row * LDW + c4 * 4 + 2] = h1;
    }
    // load X tile (64 rows x K halves), zero-pad tail rows
    for (int f = tid; f < 64 * (K / 8); f += 256) {
        int row = f / (K / 8), q = f % (K / 8);
        int grow = r0 + row;
        uint4 v = make_uint4(0, 0, 0, 0);
        if (grow < N) v = ((const uint4*)(X + (size_t)grow * K))[q];
        *(uint4*)&Xs[row * LDX + q * 8] = v;
    }
    __syncthreads();

    int wr = wid >> 1, wc = wid & 1;   // warp computes rows [wr*16, +16), cols [wc*32, +32)
    wmma::fragment<wmma::accumulator, 16, 16, 16, float> c0, c1;
    wmma::fill_fragment(c0, 0.f);
    wmma::fill_fragment(c1, 0.f);
#pragma unroll
    for (int k = 0; k < K; k += 16) {
        wmma::fragment<wmma::matrix_a, 16, 16, 16, __half, wmma::row_major> a;
        wmma::load_matrix_sync(a, Xs + wr * 16 * LDX + k, LDX);
        wmma::fragment<wmma::matrix_b, 16, 16, 16, __half, wmma::row_major> b0, b1;
        wmma::load_matrix_sync(b0, Ws + k * LDW + wc * 32, LDW);
        wmma::load_matrix_sync(b1, Ws + k * LDW + wc * 32 + 16, LDW);
        wmma::mma_sync(c0, a, b0, c0);
        wmma::mma_sync(c1, a, b1, c1);
    }
    __syncthreads();   // done reading Xs/Ws; Cs may overwrite
    wmma::store_matrix_sync(Cs + wr * 16 * LDC + wc * 32, c0, LDC, wmma::mem_row_major);
    wmma::store_matrix_sync(Cs + wr * 16 * LDC + wc * 32 + 16, c1, LDC, wmma::mem_row_major);
    __syncthreads();

    // epilogue: each thread handles row = tid>>2, 4 float4 groups
    int row = tid >> 2;
    int grow = r0 + row;
    if (grow < N) {
#pragma unroll
        for (int t = 0; t < 4; t++) {
            int cg = (tid & 3) + t * 4;   // 0..15
            float4 v = *(float4*)&Cs[row * LDC + cg * 4];
            if (HAS_SUM) {
                v.x += bias[cg * 4 + 0]; v.y += bias[cg * 4 + 1];
                v.z += bias[cg * 4 + 2]; v.w += bias[cg * 4 + 3];
                float4 s = ((const float4*)(sum + (size_t)grow * 64))[cg];
                v.x += s.x; v.y += s.y; v.z += s.z; v.w += s.w;
            }
            if (RELU) {
                v.x = fmaxf(v.x, 0.f); v.y = fmaxf(v.y, 0.f);
                v.z = fmaxf(v.z, 0.f); v.w = fmaxf(v.w, 0.f);
            }
            __half2 h0 = __floats2half2_rn(v.x, v.y);
            __half2 h1 = __floats2half2_rn(v.z, v.w);
            uint2 pk;
            pk.x = *(unsigned*)&h0;
            pk.y = *(unsigned*)&h1;
            ((uint2*)(out + (size_t)grow * 64))[cg] = pk;
        }
    }
}

// ---------------- classifier (fp16 rows): out[i] = dot(U[lu[i]], P[lp[i]]) ----
__global__ void classify_half(const int* __restrict__ lu, const int* __restrict__ lp,
                              const __half* __restrict__ U, const __half* __restrict__ P,
                              float* __restrict__ out) {
    int gid = blockIdx.x * blockDim.x + threadIdx.x;
    int e = gid >> 3;
    int c = gid & 7;
    if (e >= NLAB) return;
    int u = lu[e], p = lp[e];
    uint4 a = __ldg((const uint4*)(U + (size_t)u * 64) + c);
    uint4 b = __ldg((const uint4*)(P + (size_t)p * 64) + c);
    const unsigned* ua = (const unsigned*)&a;
    const unsigned* ub = (const unsigned*)&b;
    float s = 0.f;
#pragma unroll
    for (int k = 0; k < 4; k++) {
        float2 fa = __half22float2(*(const __half2*)&ua[k]);
        float2 fb = __half22float2(*(const __half2*)&ub[k]);
        s += fa.x * fb.x + fa.y * fb.y;
    }
    s += __shfl_down_sync(0xffffffffu, s, 4, 8);
    s += __shfl_down_sync(0xffffffffu, s, 2, 8);
    s += __shfl_down_sync(0xffffffffu, s, 1, 8);
    if (c == 0) out[e] = s;
}

// ---------------- launch ------------------------------------------------------
extern "C" void kernel_launch(void* const* d_in, const int* in_sizes, int n_in,
                              void* d_out, int out_size) {
    const float* x_user    = (const float*)d_in[0];
    const float* x_product = (const float*)d_in[1];
    const float* W1bl = (const float*)d_in[2];
    const float* b1b  = (const float*)d_in[3];
    const float* W1br = (const float*)d_in[4];
    const float* W1rl = (const float*)d_in[5];
    const float* b1r  = (const float*)d_in[6];
    const float* W1rr = (const float*)d_in[7];
    const float* W2bl = (const float*)d_in[8];
    const float* b2b  = (const float*)d_in[9];
    const float* W2br = (const float*)d_in[10];
    const float* W2rl = (const float*)d_in[11];
    const float* b2r  = (const float*)d_in[12];
    const float* W2rr = (const float*)d_in[13];
    const int* esrc = (const int*)d_in[14];
    const int* edst = (const int*)d_in[15];
    const int* lu   = (const int*)d_in[16];
    const int* lp   = (const int*)d_in[17];
    float* out = (float*)d_out;

    __half *xuh, *xph, *xu1, *xp1, *hp, *hu, *hp2, *hu2;
    float *sp, *su;
    int *histp, *histu, *rowp, *rowu, *curp, *curu, *adjp, *adju, *auxp, *auxu;
    cudaGetSymbolAddress((void**)&xuh, g_xu_h);
    cudaGetSymbolAddress((void**)&xph, g_xp_h);
    cudaGetSymbolAddress((void**)&xu1, g_xu1);
    cudaGetSymbolAddress((void**)&xp1, g_xp1);
    cudaGetSymbolAddress((void**)&sp,  g_sum_p);
    cudaGetSymbolAddress((void**)&su,  g_sum_u);
    cudaGetSymbolAddress((void**)&hp,  g_hp);
    cudaGetSymbolAddress((void**)&hu,  g_hu);
    cudaGetSymbolAddress((void**)&hp2, g_hp2);
    cudaGetSymbolAddress((void**)&hu2, g_hu2);
    cudaGetSymbolAddress((void**)&histp, g_hist_p);
    cudaGetSymbolAddress((void**)&histu, g_hist_u);
    cudaGetSymbolAddress((void**)&rowp, g_rowp_p);
    cudaGetSymbolAddress((void**)&rowu, g_rowp_u);
    cudaGetSymbolAddress((void**)&curp, g_cur_p);
    cudaGetSymbolAddress((void**)&curu, g_cur_u);
    cudaGetSymbolAddress((void**)&adjp, g_adj_p);
    cudaGetSymbolAddress((void**)&adju, g_adj_u);
    cudaGetSymbolAddress((void**)&auxp, g_aux_p);
    cudaGetSymbolAddress((void**)&auxu, g_aux_u);

    // smem sizes: max(Xs+Ws, Cs)
    const int smemG64  = 64 * (64 + 16) * 2 + 64 * 80 * 2;    // 20480
    const int smemG128 = 64 * (128 + 16) * 2 + 128 * 80 * 2;  // 38912
    const int gU = (NU + 63) / 64, gP = (NP + 63) / 64;
    const int gE = (NE + 255) / 256;
    const int gAggP = (NP * 8 + 255) / 256;
    const int gAggU = (NU * 8 + 255) / 256;
    const int gScan = CP_CHUNKS + CU_CHUNKS;

    // ---- fp16 copies of raw features ----
    conv_half_kernel<<<(NU * 64 / 4 + 255) / 256, 256>>>(x_user, xuh, NU * 64 / 4);
    conv_half_kernel<<<(NP * 128 / 4 + 255) / 256, 256>>>(x_product, xph, NP * 128 / 4);

    // ---- CSR build (both directions) ----
    zero_int_kernel<<<(NP / 4 + 255) / 256, 256>>>(histp, NP / 4);
    zero_int_kernel<<<(NU / 4 + 255) / 256, 256>>>(histu, NU / 4);
    hist_kernel<<<gE, 256>>>(esrc, edst, histp, histu);
    scan_pass1<<<gScan, 1024>>>(histp, rowp, auxp, histu, rowu, auxu);
    scan_pass2<<<2, 32>>>(auxp, rowp, auxu, rowu);
    scan_pass3<<<gScan, 1024>>>(rowp, auxp, curp, rowu, auxu, curu);
    fill_kernel<<<gE, 256>>>(esrc, edst, curp, curu, adjp, adju);

    // ---- layer 1 ----
    gemm_wmma<64, false, false><<<gU, 256, smemG64>>>(xuh, W1bl, nullptr, nullptr, xu1, NU);
    gemm_wmma<128, false, false><<<gP, 256, smemG128>>>(xph, W1rl, nullptr, nullptr, xp1, NP);
    gather_mean_half<<<gAggP, 256>>>(rowp, adjp, xu1, sp, NP);
    gather_mean_half<<<gAggU, 256>>>(rowu, adju, xp1, su, NU);
    gemm_wmma<128, true, true><<<gP, 256, smemG128>>>(xph, W1br, b1b, sp, hp, NP);
    gemm_wmma<64, true, true><<<gU, 256, smemG64>>>(xuh, W1rr, b1r, su, hu, NU);

    // ---- layer 2 ----
    gemm_wmma<64, false, false><<<gU, 256, smemG64>>>(hu, W2bl, nullptr, nullptr, xu1, NU);
    gemm_wmma<64, false, false><<<gP, 256, smemG64>>>(hp, W2rl, nullptr, nullptr, xp1, NP);
    gather_mean_half<<<gAggP, 256>>>(rowp, adjp, xu1, sp, NP);
    gather_mean_half<<<gAggU, 256>>>(rowu, adju, xp1, su, NU);
    gemm_wmma<64, true, false><<<gP, 256, smemG64>>>(hp, W2br, b2b, sp, hp2, NP);
    gemm_wmma<64, true, false><<<gU, 256, smemG64>>>(hu, W2rr, b2r, su, hu2, NU);

    // ---- classifier ----
    classify_half<<<(NLAB * 8 + 255) / 256, 256>>>(lu, lp, hu2, hp2, out);
}

// round 11
// speedup vs baseline: 2.0831x; 1.0137x over previous
#include <cuda_runtime.h>
#include <cuda_fp16.h>
#include <mma.h>
#include <cstddef>

using namespace nvcuda;

#define NU 100000
#define NP 50000
#define NE 2000000
#define NLAB 500000
#define HDIM 64

#define CHUNK 4096
#define CP_CHUNKS ((NP + CHUNK - 1) / CHUNK)   // 13
#define CU_CHUNKS ((NU + CHUNK - 1) / CHUNK)   // 25

// ---------------- scratch (device globals; no allocation allowed) -------------
__device__ __half g_xu_h[NU * 64];     // fp16 copy of x_user
__device__ __half g_xp_h[NP * 128];    // fp16 copy of x_product
__device__ __half g_xu1[NU * HDIM];    // projected user feats (fp16)
__device__ __half g_xp1[NP * HDIM];    // projected product feats (fp16)
__device__ __half g_hp[NP * HDIM];
__device__ __half g_hu[NU * HDIM];
__device__ __half g_hp2[NP * HDIM];
__device__ __half g_hu2[NU * HDIM];

__device__ int g_hist_p[NP];
__device__ int g_hist_u[NU];
__device__ int g_rowp_p[NP + 1];
__device__ int g_rowp_u[NU + 1];
__device__ int g_cur_p[NP];
__device__ int g_cur_u[NU];
__device__ int g_adj_p[NE];
__device__ int g_adj_u[NE];
__device__ int g_aux_p[32];
__device__ int g_aux_u[32];

// ---------------- utility ----------------------------------------------------
__global__ void zero2_kernel(int* __restrict__ p0, int n0, int* __restrict__ p1, int n1) {
    int i = blockIdx.x * blockDim.x + threadIdx.x;
    if (i < n0) ((int4*)p0)[i] = make_int4(0, 0, 0, 0);
    else if (i < n0 + n1) ((int4*)p1)[i - n0] = make_int4(0, 0, 0, 0);
}

__global__ void conv2_kernel(const float* __restrict__ a, __half* __restrict__ oa, int na,
                             const float* __restrict__ b, __half* __restrict__ ob, int nb) {
    int i = blockIdx.x * blockDim.x + threadIdx.x;
    const float* in; __half* out; int idx;
    if (i < na) { in = a; out = oa; idx = i; }
    else if (i < na + nb) { in = b; out = ob; idx = i - na; }
    else return;
    float4 v = ((const float4*)in)[idx];
    __half2 h0 = __floats2half2_rn(v.x, v.y);
    __half2 h1 = __floats2half2_rn(v.z, v.w);
    uint2 pk;
    pk.x = *(unsigned*)&h0;
    pk.y = *(unsigned*)&h1;
    ((uint2*)out)[idx] = pk;
}

// ---------------- CSR build ---------------------------------------------------
__global__ void hist_kernel(const int* __restrict__ src, const int* __restrict__ dst,
                            int* __restrict__ hp, int* __restrict__ hu) {
    int e = blockIdx.x * blockDim.x + threadIdx.x;
    if (e >= NE) return;
    atomicAdd(hp + dst[e], 1);
    atomicAdd(hu + src[e], 1);
}

__global__ void scan_pass1(const int* __restrict__ hP, int* __restrict__ rP, int* __restrict__ auxP,
                           const int* __restrict__ hU, int* __restrict__ rU, int* __restrict__ auxU) {
    int b = blockIdx.x;
    const int* h; int* r; int* aux; int n; int cid;
    if (b < CP_CHUNKS) { h = hP; r = rP; aux = auxP; n = NP; cid = b; }
    else               { h = hU; r = rU; aux = auxU; n = NU; cid = b - CP_CHUNKS; }

    int tid = threadIdx.x;
    int base = cid * CHUNK + tid * 4;
    int4 v = make_int4(0, 0, 0, 0);
    if (base < n) v = *(const int4*)(h + base);
    int tsum = v.x + v.y + v.z + v.w;

    unsigned lane = tid & 31, wid = tid >> 5;
    int inc = tsum;
#pragma unroll
    for (int off = 1; off < 32; off <<= 1) {
        int t = __shfl_up_sync(0xffffffffu, inc, off);
        if (lane >= off) inc += t;
    }
    __shared__ int s_w[32];
    if (lane == 31) s_w[wid] = inc;
    __syncthreads();
    if (tid < 32) {
        int w = s_w[tid];
        int winc = w;
#pragma unroll
        for (int off = 1; off < 32; off <<= 1) {
            int t = __shfl_up_sync(0xffffffffu, winc, off);
            if (tid >= off) winc += t;
        }
        s_w[tid] = winc - w;
        if (tid == 31) aux[cid] = winc;
    }
    __syncthreads();
    int tbase = s_w[wid] + inc - tsum;
    if (base < n) {
        int4 o;
        o.x = tbase;
        o.y = tbase + v.x;
        o.z = o.y + v.y;
        o.w = o.z + v.z;
        *(int4*)(r + base) = o;
    }
}

__global__ void scan_pass2(int* __restrict__ auxP, int* __restrict__ rP,
                           int* __restrict__ auxU, int* __restrict__ rU) {
    int* aux; int* r; int cnt; int n;
    if (blockIdx.x == 0) { aux = auxP; r = rP; cnt = CP_CHUNKS; n = NP; }
    else                 { aux = auxU; r = rU; cnt = CU_CHUNKS; n = NU; }
    int tid = threadIdx.x;
    int a = (tid < cnt) ? aux[tid] : 0;
    int inc = a;
#pragma unroll
    for (int off = 1; off < 32; off <<= 1) {
        int t = __shfl_up_sync(0xffffffffu, inc, off);
        if (tid >= off) inc += t;
    }
    if (tid < cnt) aux[tid] = inc - a;
    if (tid == 31) r[n] = inc;
}

__global__ void scan_pass3(int* __restrict__ rP, const int* __restrict__ auxP, int* __restrict__ cP,
                           int* __restrict__ rU, const int* __restrict__ auxU, int* __restrict__ cU) {
    int b = blockIdx.x;
    int* r; const int* aux; int* c; int n; int cid;
    if (b < CP_CHUNKS) { r = rP; aux = auxP; c = cP; n = NP; cid = b; }
    else               { r = rU; aux = auxU; c = cU; n = NU; cid = b - CP_CHUNKS; }
    int tid = threadIdx.x;
    int base = cid * CHUNK + tid * 4;
    if (base >= n) return;
    int off = aux[cid];
    int4 v = *(const int4*)(r + base);
    v.x += off; v.y += off; v.z += off; v.w += off;
    *(int4*)(r + base) = v;
    *(int4*)(c + base) = v;
}

__global__ void fill_kernel(const int* __restrict__ src, const int* __restrict__ dst,
                            int* __restrict__ cur_p, int* __restrict__ cur_u,
                            int* __restrict__ adj_p, int* __restrict__ adj_u) {
    int e = blockIdx.x * blockDim.x + threadIdx.x;
    if (e >= NE) return;
    int s = src[e], d = dst[e];
    int pp = atomicAdd(cur_p + d, 1);
    adj_p[pp] = s;
    int pu = atomicAdd(cur_u + s, 1);
    adj_u[pu] = d;
}

// ---------------- projection GEMM: out[N,64](fp16) = X[N,K](fp16) @ W(fp32->fp16)
template <int K>
__global__ void gemm_proj(const __half* __restrict__ X, const float* __restrict__ W,
                          __half* __restrict__ out, int N) {
    constexpr int LDX = K + 16;
    constexpr int LDW = 80;
    constexpr int LDC = 80;
    extern __shared__ char smem_raw[];
    __half* Xs = (__half*)smem_raw;
    __half* Ws = (__half*)(smem_raw + 64 * LDX * 2);
    float*  Cs = (float*)smem_raw;

    int tid = threadIdx.x;
    int wid = tid >> 5;
    int r0 = blockIdx.x * 64;

    for (int f = tid; f < K * 16; f += 256) {
        int row = f >> 4, c4 = f & 15;
        float4 w = ((const float4*)(W + row * 64))[c4];
        __half2 h0 = __floats2half2_rn(w.x, w.y);
        __half2 h1 = __floats2half2_rn(w.z, w.w);
        *(__half2*)&Ws[row * LDW + c4 * 4] = h0;
        *(__half2*)&Ws[row * LDW + c4 * 4 + 2] = h1;
    }
    for (int f = tid; f < 64 * (K / 8); f += 256) {
        int row = f / (K / 8), q = f % (K / 8);
        int grow = r0 + row;
        uint4 v = make_uint4(0, 0, 0, 0);
        if (grow < N) v = ((const uint4*)(X + (size_t)grow * K))[q];
        *(uint4*)&Xs[row * LDX + q * 8] = v;
    }
    __syncthreads();

    int wr = wid >> 1, wc = wid & 1;
    wmma::fragment<wmma::accumulator, 16, 16, 16, float> c0, c1;
    wmma::fill_fragment(c0, 0.f);
    wmma::fill_fragment(c1, 0.f);
#pragma unroll
    for (int k = 0; k < K; k += 16) {
        wmma::fragment<wmma::matrix_a, 16, 16, 16, __half, wmma::row_major> a;
        wmma::load_matrix_sync(a, Xs + wr * 16 * LDX + k, LDX);
        wmma::fragment<wmma::matrix_b, 16, 16, 16, __half, wmma::row_major> b0, b1;
        wmma::load_matrix_sync(b0, Ws + k * LDW + wc * 32, LDW);
        wmma::load_matrix_sync(b1, Ws + k * LDW + wc * 32 + 16, LDW);
        wmma::mma_sync(c0, a, b0, c0);
        wmma::mma_sync(c1, a, b1, c1);
    }
    __syncthreads();
    wmma::store_matrix_sync(Cs + wr * 16 * LDC + wc * 32, c0, LDC, wmma::mem_row_major);
    wmma::store_matrix_sync(Cs + wr * 16 * LDC + wc * 32 + 16, c1, LDC, wmma::mem_row_major);
    __syncthreads();

    int row = tid >> 2;
    int grow = r0 + row;
    if (grow < N) {
#pragma unroll
        for (int t = 0; t < 4; t++) {
            int cg = (tid & 3) + t * 4;
            float4 v = *(float4*)&Cs[row * LDC + cg * 4];
            __half2 h0 = __floats2half2_rn(v.x, v.y);
            __half2 h1 = __floats2half2_rn(v.z, v.w);
            uint2 pk;
            pk.x = *(unsigned*)&h0;
            pk.y = *(unsigned*)&h1;
            ((uint2*)(out + (size_t)grow * 64))[cg] = pk;
        }
    }
}

// ---------------- fused combine GEMM + gather-mean ----------------------------
// out = [gather_mean(Agg over CSR) + X@W + bias] (relu optional), all rows fp16.
template <int K, bool RELU>
__global__ void gemm_combine(const __half* __restrict__ X, const float* __restrict__ W,
                             const float* __restrict__ bias,
                             const int* __restrict__ rowptr, const int* __restrict__ adj,
                             const __half* __restrict__ Agg,
                             __half* __restrict__ out, int N) {
    constexpr int LDX = K + 16;
    constexpr int LDW = 80;
    constexpr int LDC = 80;
    extern __shared__ char smem_raw[];
    __half* Xs = (__half*)smem_raw;
    __half* Ws = (__half*)(smem_raw + 64 * LDX * 2);
    float*  Cs = (float*)smem_raw;

    int tid = threadIdx.x;
    int wid = tid >> 5;
    int r0 = blockIdx.x * 64;

    for (int f = tid; f < K * 16; f += 256) {
        int row = f >> 4, c4 = f & 15;
        float4 w = ((const float4*)(W + row * 64))[c4];
        __half2 h0 = __floats2half2_rn(w.x, w.y);
        __half2 h1 = __floats2half2_rn(w.z, w.w);
        *(__half2*)&Ws[row * LDW + c4 * 4] = h0;
        *(__half2*)&Ws[row * LDW + c4 * 4 + 2] = h1;
    }
    for (int f = tid; f < 64 * (K / 8); f += 256) {
        int row = f / (K / 8), q = f % (K / 8);
        int grow = r0 + row;
        uint4 v = make_uint4(0, 0, 0, 0);
        if (grow < N) v = ((const uint4*)(X + (size_t)grow * K))[q];
        *(uint4*)&Xs[row * LDX + q * 8] = v;
    }
    __syncthreads();

    int wr = wid >> 1, wc = wid & 1;
    wmma::fragment<wmma::accumulator, 16, 16, 16, float> c0, c1;
    wmma::fill_fragment(c0, 0.f);
    wmma::fill_fragment(c1, 0.f);
#pragma unroll
    for (int k = 0; k < K; k += 16) {
        wmma::fragment<wmma::matrix_a, 16, 16, 16, __half, wmma::row_major> a;
        wmma::load_matrix_sync(a, Xs + wr * 16 * LDX + k, LDX);
        wmma::fragment<wmma::matrix_b, 16, 16, 16, __half, wmma::row_major> b0, b1;
        wmma::load_matrix_sync(b0, Ws + k * LDW + wc * 32, LDW);
        wmma::load_matrix_sync(b1, Ws + k * LDW + wc * 32 + 16, LDW);
        wmma::mma_sync(c0, a, b0, c0);
        wmma::mma_sync(c1, a, b1, c1);
    }
    __syncthreads();
    wmma::store_matrix_sync(Cs + wr * 16 * LDC + wc * 32, c0, LDC, wmma::mem_row_major);
    wmma::store_matrix_sync(Cs + wr * 16 * LDC + wc * 32 + 16, c1, LDC, wmma::mem_row_major);
    __syncthreads();

    // ---- gather + epilogue: 4 threads per node; thread handles 16 halves ----
    int row = tid >> 2;          // 0..63
    int cq  = tid & 3;           // quarter of the 64-dim row
    int node = r0 + row;
    if (node >= N) return;       // no __syncthreads below

    int beg = __ldg(rowptr + node), end = __ldg(rowptr + node + 1);
    float acc[16];
#pragma unroll
    for (int i = 0; i < 16; i++) acc[i] = 0.f;

    int j = beg;
    for (; j + 2 <= end; j += 2) {
        int i0 = __ldg(adj + j), i1 = __ldg(adj + j + 1);
        const uint4* pa = (const uint4*)(Agg + (size_t)i0 * 64) + cq * 2;
        uint4 a0 = __ldg(pa), a1 = __ldg(pa + 1);
        const uint4* pb = (const uint4*)(Agg + (size_t)i1 * 64) + cq * 2;
        uint4 b0 = __ldg(pb), b1 = __ldg(pb + 1);
        const unsigned* ua0 = (const unsigned*)&a0;
        const unsigned* ua1 = (const unsigned*)&a1;
        const unsigned* ub0 = (const unsigned*)&b0;
        const unsigned* ub1 = (const unsigned*)&b1;
#pragma unroll
        for (int k = 0; k < 4; k++) {
            float2 f0 = __half22float2(*(const __half2*)&ua0[k]);
            float2 f1 = __half22float2(*(const __half2*)&ua1[k]);
            float2 g0 = __half22float2(*(const __half2*)&ub0[k]);
            float2 g1 = __half22float2(*(const __half2*)&ub1[k]);
            acc[k * 2]         += f0.x + g0.x;
            acc[k * 2 + 1]     += f0.y + g0.y;
            acc[8 + k * 2]     += f1.x + g1.x;
            acc[8 + k * 2 + 1] += f1.y + g1.y;
        }
    }
    if (j < end) {
        int i0 = __ldg(adj + j);
        const uint4* pa = (const uint4*)(Agg + (size_t)i0 * 64) + cq * 2;
        uint4 a0 = __ldg(pa), a1 = __ldg(pa + 1);
        const unsigned* ua0 = (const unsigned*)&a0;
        const unsigned* ua1 = (const unsigned*)&a1;
#pragma unroll
        for (int k = 0; k < 4; k++) {
            float2 f0 = __half22float2(*(const __half2*)&ua0[k]);
            float2 f1 = __half22float2(*(const __half2*)&ua1[k]);
            acc[k * 2]         += f0.x;
            acc[k * 2 + 1]     += f0.y;
            acc[8 + k * 2]     += f1.x;
            acc[8 + k * 2 + 1] += f1.y;
        }
    }
    float rc = 1.f / fmaxf((float)(end - beg), 1.f);

    unsigned st[8];
#pragma unroll
    for (int t = 0; t < 4; t++) {
        int c0i = cq * 16 + t * 4;
        float4 v = *(float4*)&Cs[row * LDC + c0i];
        v.x += acc[t * 4 + 0] * rc + bias[c0i + 0];
        v.y += acc[t * 4 + 1] * rc + bias[c0i + 1];
        v.z += acc[t * 4 + 2] * rc + bias[c0i + 2];
        v.w += acc[t * 4 + 3] * rc + bias[c0i + 3];
        if (RELU) {
            v.x = fmaxf(v.x, 0.f); v.y = fmaxf(v.y, 0.f);
            v.z = fmaxf(v.z, 0.f); v.w = fmaxf(v.w, 0.f);
        }
        __half2 h0 = __floats2half2_rn(v.x, v.y);
        __half2 h1 = __floats2half2_rn(v.z, v.w);
        st[t * 2]     = *(unsigned*)&h0;
        st[t * 2 + 1] = *(unsigned*)&h1;
    }
    uint4* dst = (uint4*)(out + (size_t)node * 64 + cq * 16);
    dst[0] = make_uint4(st[0], st[1], st[2], st[3]);
    dst[1] = make_uint4(st[4], st[5], st[6], st[7]);
}

// ---------------- classifier (fp16 rows) --------------------------------------
__global__ void classify_half(const int* __restrict__ lu, const int* __restrict__ lp,
                              const __half* __restrict__ U, const __half* __restrict__ P,
                              float* __restrict__ out) {
    int gid = blockIdx.x * blockDim.x + threadIdx.x;
    int e = gid >> 3;
    int c = gid & 7;
    if (e >= NLAB) return;
    int u = lu[e], p = lp[e];
    uint4 a = __ldg((const uint4*)(U + (size_t)u * 64) + c);
    uint4 b = __ldg((const uint4*)(P + (size_t)p * 64) + c);
    const unsigned* ua = (const unsigned*)&a;
    const unsigned* ub = (const unsigned*)&b;
    float s = 0.f;
#pragma unroll
    for (int k = 0; k < 4; k++) {
        float2 fa = __half22float2(*(const __half2*)&ua[k]);
        float2 fb = __half22float2(*(const __half2*)&ub[k]);
        s += fa.x * fb.x + fa.y * fb.y;
    }
    s += __shfl_down_sync(0xffffffffu, s, 4, 8);
    s += __shfl_down_sync(0xffffffffu, s, 2, 8);
    s += __shfl_down_sync(0xffffffffu, s, 1, 8);
    if (c == 0) out[e] = s;
}

// ---------------- launch ------------------------------------------------------
extern "C" void kernel_launch(void* const* d_in, const int* in_sizes, int n_in,
                              void* d_out, int out_size) {
    const float* x_user    = (const float*)d_in[0];
    const float* x_product = (const float*)d_in[1];
    const float* W1bl = (const float*)d_in[2];
    const float* b1b  = (const float*)d_in[3];
    const float* W1br = (const float*)d_in[4];
    const float* W1rl = (const float*)d_in[5];
    const float* b1r  = (const float*)d_in[6];
    const float* W1rr = (const float*)d_in[7];
    const float* W2bl = (const float*)d_in[8];
    const float* b2b  = (const float*)d_in[9];
    const float* W2br = (const float*)d_in[10];
    const float* W2rl = (const float*)d_in[11];
    const float* b2r  = (const float*)d_in[12];
    const float* W2rr = (const float*)d_in[13];
    const int* esrc = (const int*)d_in[14];
    const int* edst = (const int*)d_in[15];
    const int* lu   = (const int*)d_in[16];
    const int* lp   = (const int*)d_in[17];
    float* out = (float*)d_out;

    __half *xuh, *xph, *xu1, *xp1, *hp, *hu, *hp2, *hu2;
    int *histp, *histu, *rowp, *rowu, *curp, *curu, *adjp, *adju, *auxp, *auxu;
    cudaGetSymbolAddress((void**)&xuh, g_xu_h);
    cudaGetSymbolAddress((void**)&xph, g_xp_h);
    cudaGetSymbolAddress((void**)&xu1, g_xu1);
    cudaGetSymbolAddress((void**)&xp1, g_xp1);
    cudaGetSymbolAddress((void**)&hp,  g_hp);
    cudaGetSymbolAddress((void**)&hu,  g_hu);
    cudaGetSymbolAddress((void**)&hp2, g_hp2);
    cudaGetSymbolAddress((void**)&hu2, g_hu2);
    cudaGetSymbolAddress((void**)&histp, g_hist_p);
    cudaGetSymbolAddress((void**)&histu, g_hist_u);
    cudaGetSymbolAddress((void**)&rowp, g_rowp_p);
    cudaGetSymbolAddress((void**)&rowu, g_rowp_u);
    cudaGetSymbolAddress((void**)&curp, g_cur_p);
    cudaGetSymbolAddress((void**)&curu, g_cur_u);
    cudaGetSymbolAddress((void**)&adjp, g_adj_p);
    cudaGetSymbolAddress((void**)&adju, g_adj_u);
    cudaGetSymbolAddress((void**)&auxp, g_aux_p);
    cudaGetSymbolAddress((void**)&auxu, g_aux_u);

    const int smemG64  = 64 * (64 + 16) * 2 + 64 * 80 * 2;    // 20480
    const int smemG128 = 64 * (128 + 16) * 2 + 128 * 80 * 2;  // 38912
    const int gU = (NU + 63) / 64, gP = (NP + 63) / 64;
    const int gE = (NE + 255) / 256;
    const int gScan = CP_CHUNKS + CU_CHUNKS;

    // ---- fp16 conversion (both tables, one launch) ----
    const int nCu = NU * 64 / 4, nCp = NP * 128 / 4;
    conv2_kernel<<<(nCu + nCp + 255) / 256, 256>>>(x_user, xuh, nCu, x_product, xph, nCp);

    // ---- CSR build ----
    zero2_kernel<<<(NP / 4 + NU / 4 + 255) / 256, 256>>>(histp, NP / 4, histu, NU / 4);
    hist_kernel<<<gE, 256>>>(esrc, edst, histp, histu);
    scan_pass1<<<gScan, 1024>>>(histp, rowp, auxp, histu, rowu, auxu);
    scan_pass2<<<2, 32>>>(auxp, rowp, auxu, rowu);
    scan_pass3<<<gScan, 1024>>>(rowp, auxp, curp, rowu, auxu, curu);
    fill_kernel<<<gE, 256>>>(esrc, edst, curp, curu, adjp, adju);

    // ---- layer 1 ----
    gemm_proj<64><<<gU, 256, smemG64>>>(xuh, W1bl, xu1, NU);
    gemm_proj<128><<<gP, 256, smemG128>>>(xph, W1rl, xp1, NP);
    gemm_combine<128, true><<<gP, 256, smemG128>>>(xph, W1br, b1b, rowp, adjp, xu1, hp, NP);
    gemm_combine<64, true><<<gU, 256, smemG64>>>(xuh, W1rr, b1r, rowu, adju, xp1, hu, NU);

    // ---- layer 2 ----
    gemm_proj<64><<<gU, 256, smemG64>>>(hu, W2bl, xu1, NU);
    gemm_proj<64><<<gP, 256, smemG64>>>(hp, W2rl, xp1, NP);
    gemm_combine<64, false><<<gP, 256, smemG64>>>(hp, W2br, b2b, rowp, adjp, xu1, hp2, NP);
    gemm_combine<64, false><<<gU, 256, smemG64>>>(hu, W2rr, b2r, rowu, adju, xp1, hu2, NU);

    // ---- classifier ----
    classify_half<<<(NLAB * 8 + 255) / 256, 256>>>(lu, lp, hu2, hp2, out);
}